// round 1
// baseline (speedup 1.0000x reference)
#include <cuda_runtime.h>
#include <math.h>

// Problem constants: B=4, T=2048, E=1024, H*D=1024
#define BBATCH 4
#define TSEQ   2048
#define EDIM   1024

// ---------------- scratch (device globals: zero-initialized at load) -------
__device__ float g_Wc[EDIM * EDIM];                     // wo @ wjv   (4 MB)
__device__ float g_y [BBATCH * TSEQ * EDIM];            // x @ wj^T   (32 MB)
__device__ float g_u [BBATCH * TSEQ * EDIM];            // x @ Wc^T   (32 MB)
__device__ float g_P [(size_t)BBATCH * TSEQ * TSEQ];    // unnorm probs (64 MB)
__device__ float g_sc  [BBATCH * TSEQ];
__device__ float g_cmax[BBATCH * TSEQ];
__device__ float g_Z   [BBATCH * TSEQ];

// ---------------- SGEMM NT: C[m,n] = sum_k A[m,k] * B[n,k] ----------------
// A: (M,K) row-major, B: (N,K) row-major. M,N % 128 == 0, K % 16 == 0.
__global__ __launch_bounds__(256) void sgemm_nt(
    const float* __restrict__ A, const float* __restrict__ B,
    float* __restrict__ C, int M, int N, int K)
{
    __shared__ float As[16][128];
    __shared__ float Bs[16][128];
    const int tid = threadIdx.x;
    const int m0 = blockIdx.y * 128;
    const int n0 = blockIdx.x * 128;
    const int tm = (tid >> 4) << 3;
    const int tn = (tid & 15) << 3;
    const int lr = tid >> 2;          // 0..63
    const int lc = (tid & 3) << 2;    // 0,4,8,12

    float acc[8][8];
#pragma unroll
    for (int i = 0; i < 8; ++i)
#pragma unroll
        for (int j = 0; j < 8; ++j) acc[i][j] = 0.f;

    for (int k0 = 0; k0 < K; k0 += 16) {
#pragma unroll
        for (int h = 0; h < 2; ++h) {
            int r = lr + h * 64;
            float4 a = *(const float4*)(A + (size_t)(m0 + r) * K + k0 + lc);
            As[lc + 0][r] = a.x; As[lc + 1][r] = a.y;
            As[lc + 2][r] = a.z; As[lc + 3][r] = a.w;
            float4 bv = *(const float4*)(B + (size_t)(n0 + r) * K + k0 + lc);
            Bs[lc + 0][r] = bv.x; Bs[lc + 1][r] = bv.y;
            Bs[lc + 2][r] = bv.z; Bs[lc + 3][r] = bv.w;
        }
        __syncthreads();
#pragma unroll
        for (int k = 0; k < 16; ++k) {
            float ra[8], rb[8];
            *(float4*)(ra)     = *(const float4*)&As[k][tm];
            *(float4*)(ra + 4) = *(const float4*)&As[k][tm + 4];
            *(float4*)(rb)     = *(const float4*)&Bs[k][tn];
            *(float4*)(rb + 4) = *(const float4*)&Bs[k][tn + 4];
#pragma unroll
            for (int i = 0; i < 8; ++i)
#pragma unroll
                for (int j = 0; j < 8; ++j)
                    acc[i][j] = fmaf(ra[i], rb[j], acc[i][j]);
        }
        __syncthreads();
    }
#pragma unroll
    for (int i = 0; i < 8; ++i) {
        float* Cp = C + (size_t)(m0 + tm + i) * N + n0 + tn;
        float4 c0 = make_float4(acc[i][0], acc[i][1], acc[i][2], acc[i][3]);
        float4 c1 = make_float4(acc[i][4], acc[i][5], acc[i][6], acc[i][7]);
        *(float4*)(Cp)     = c0;
        *(float4*)(Cp + 4) = c1;
    }
}

// ---------------- SGEMM NN: C[m,n] = sum_k A[m,k] * B[k,n] ----------------
// A: (M,K) row-major, B: (K,N) row-major. Optional batch strides, causal
// K-limit (A strict-upper is zero so k < m0+128 suffices), and 1/Z row scale.
__global__ __launch_bounds__(256) void sgemm_nn(
    const float* __restrict__ A, const float* __restrict__ B,
    float* __restrict__ C, int M, int N, int K,
    long long sA, long long sB, long long sC,
    const float* __restrict__ Z, int causal)
{
    const int bz = blockIdx.z;
    A += (size_t)bz * sA; B += (size_t)bz * sB; C += (size_t)bz * sC;

    __shared__ float As[16][128];
    __shared__ float Bs[16][128];
    const int tid = threadIdx.x;
    const int m0 = blockIdx.y * 128;
    const int n0 = blockIdx.x * 128;
    const int tm = (tid >> 4) << 3;
    const int tn = (tid & 15) << 3;
    const int lr = tid >> 2;          // A loader: 0..63
    const int lc = (tid & 3) << 2;
    const int kr = tid >> 5;          // B loader: 0..7
    const int nc = (tid & 31) << 2;   // 0..124

    const int kEnd = causal ? ((m0 + 128 < K) ? (m0 + 128) : K) : K;

    float acc[8][8];
#pragma unroll
    for (int i = 0; i < 8; ++i)
#pragma unroll
        for (int j = 0; j < 8; ++j) acc[i][j] = 0.f;

    for (int k0 = 0; k0 < kEnd; k0 += 16) {
#pragma unroll
        for (int h = 0; h < 2; ++h) {
            int r = lr + h * 64;
            float4 a = *(const float4*)(A + (size_t)(m0 + r) * K + k0 + lc);
            As[lc + 0][r] = a.x; As[lc + 1][r] = a.y;
            As[lc + 2][r] = a.z; As[lc + 3][r] = a.w;
            float4 bv = *(const float4*)(B + (size_t)(k0 + kr + h * 8) * N + n0 + nc);
            *(float4*)&Bs[kr + h * 8][nc] = bv;
        }
        __syncthreads();
#pragma unroll
        for (int k = 0; k < 16; ++k) {
            float ra[8], rb[8];
            *(float4*)(ra)     = *(const float4*)&As[k][tm];
            *(float4*)(ra + 4) = *(const float4*)&As[k][tm + 4];
            *(float4*)(rb)     = *(const float4*)&Bs[k][tn];
            *(float4*)(rb + 4) = *(const float4*)&Bs[k][tn + 4];
#pragma unroll
            for (int i = 0; i < 8; ++i)
#pragma unroll
                for (int j = 0; j < 8; ++j)
                    acc[i][j] = fmaf(ra[i], rb[j], acc[i][j]);
        }
        __syncthreads();
    }
#pragma unroll
    for (int i = 0; i < 8; ++i) {
        float scale = 1.f;
        if (Z) scale = 1.f / Z[(size_t)bz * M + m0 + tm + i];
        float* Cp = C + (size_t)(m0 + tm + i) * N + n0 + tn;
        float4 c0 = make_float4(acc[i][0] * scale, acc[i][1] * scale,
                                acc[i][2] * scale, acc[i][3] * scale);
        float4 c1 = make_float4(acc[i][4] * scale, acc[i][5] * scale,
                                acc[i][6] * scale, acc[i][7] * scale);
        *(float4*)(Cp)     = c0;
        *(float4*)(Cp + 4) = c1;
    }
}

// ------------- sc[t] = ||y_t||^2 / sqrt(E); one block per token ------------
__global__ __launch_bounds__(256) void sc_kernel()
{
    const int row = blockIdx.x;
    const float* yr = g_y + (size_t)row * EDIM;
    float s = 0.f;
    for (int i = threadIdx.x * 4; i < EDIM; i += 256 * 4) {
        float4 v = *(const float4*)&yr[i];
        s = fmaf(v.x, v.x, fmaf(v.y, v.y, fmaf(v.z, v.z, fmaf(v.w, v.w, s))));
    }
#pragma unroll
    for (int o = 16; o; o >>= 1) s += __shfl_xor_sync(0xffffffffu, s, o);
    __shared__ float red[8];
    if ((threadIdx.x & 31) == 0) red[threadIdx.x >> 5] = s;
    __syncthreads();
    if (threadIdx.x < 8) {
        float v = red[threadIdx.x];
#pragma unroll
        for (int o = 4; o; o >>= 1) v += __shfl_xor_sync(0xffu, v, o);
        if (threadIdx.x == 0) g_sc[row] = v * 0.03125f;   // 1/sqrt(1024)
    }
}

// --------------- inclusive cummax of sc per batch (max-scan) ---------------
__global__ __launch_bounds__(1024) void cummax_kernel()
{
    __shared__ float s[TSEQ];
    const int b = blockIdx.x;
    const int tid = threadIdx.x;
    s[tid]        = g_sc[b * TSEQ + tid];
    s[tid + 1024] = g_sc[b * TSEQ + tid + 1024];
    __syncthreads();
    for (int off = 1; off < TSEQ; off <<= 1) {
        float v0 = s[tid];
        if (tid >= off) v0 = fmaxf(v0, s[tid - off]);
        float v1 = fmaxf(s[tid + 1024], s[tid + 1024 - off]);
        __syncthreads();
        s[tid] = v0; s[tid + 1024] = v1;
        __syncthreads();
    }
    g_cmax[b * TSEQ + tid]        = s[tid];
    g_cmax[b * TSEQ + tid + 1024] = s[tid + 1024];
}

// ------- P[b,t,s] = exp(sc_t*sc_s - sc_t*cmax_t) for s<=t, Z = rowsum ------
// Strict-upper tiles are never written: device globals are zero-initialized
// and stay zero. Deterministic (no atomics).
__global__ __launch_bounds__(256) void pgen_kernel()
{
    const int b = blockIdx.y;
    const int t0 = blockIdx.x * 32;
    const int warp = threadIdx.x >> 5, lane = threadIdx.x & 31;
    const float* scb = g_sc + b * TSEQ;
    float* Pb = g_P + (size_t)b * TSEQ * TSEQ;
#pragma unroll
    for (int r = 0; r < 4; ++r) {
        const int t = t0 + warp * 4 + r;
        const float st = scb[t];
        const float m = st * g_cmax[b * TSEQ + t];
        float rowsum = 0.f;
        float* Pr = Pb + (size_t)t * TSEQ;
        for (int sb = lane * 4; sb <= t; sb += 128) {
            float4 sv = *(const float4*)&scb[sb];
            float4 p;
            p.x = (sb + 0 <= t) ? __expf(fmaf(st, sv.x, -m)) : 0.f;
            p.y = (sb + 1 <= t) ? __expf(fmaf(st, sv.y, -m)) : 0.f;
            p.z = (sb + 2 <= t) ? __expf(fmaf(st, sv.z, -m)) : 0.f;
            p.w = (sb + 3 <= t) ? __expf(fmaf(st, sv.w, -m)) : 0.f;
            *(float4*)&Pr[sb] = p;
            rowsum += (p.x + p.y) + (p.z + p.w);
        }
#pragma unroll
        for (int o = 16; o; o >>= 1)
            rowsum += __shfl_xor_sync(0xffffffffu, rowsum, o);
        if (lane == 0) g_Z[b * TSEQ + t] = rowsum;
    }
}

// --------------------------------- launch ----------------------------------
extern "C" void kernel_launch(void* const* d_in, const int* in_sizes, int n_in,
                              void* d_out, int out_size)
{
    const float* x   = (const float*)d_in[0];
    const float* wj  = (const float*)d_in[1];
    const float* wjv = (const float*)d_in[2];
    const float* wo  = (const float*)d_in[3];
    float* out = (float*)d_out;

    float *Wc, *y, *u, *P, *Z;
    cudaGetSymbolAddress((void**)&Wc, g_Wc);
    cudaGetSymbolAddress((void**)&y,  g_y);
    cudaGetSymbolAddress((void**)&u,  g_u);
    cudaGetSymbolAddress((void**)&P,  g_P);
    cudaGetSymbolAddress((void**)&Z,  g_Z);

    const int M = BBATCH * TSEQ;   // 8192 token rows
    const int T = TSEQ, E = EDIM;

    // 1. y = x @ wj^T  (fp32: sc precision is critical)
    sgemm_nt<<<dim3(E / 128, M / 128), 256>>>(x, wj, y, M, E, E);
    // 2. sc_t = ||y_t||^2 / 32
    sc_kernel<<<M, 256>>>();
    // 3. per-batch cummax(sc)  -> exact row max of logits
    cummax_kernel<<<BBATCH, 1024>>>();
    // 4. P (unnormalized probs, causal) + row sums Z
    pgen_kernel<<<dim3(T / 32, BBATCH), 256>>>();
    // 5. Wc = wo @ wjv  (folded value/output projection)
    sgemm_nn<<<dim3(E / 128, E / 128, 1), 256>>>(wo, wjv, Wc, E, E, E,
                                                 0, 0, 0, nullptr, 0);
    // 6. u = x @ Wc^T
    sgemm_nt<<<dim3(E / 128, M / 128), 256>>>(x, Wc, u, M, E, E);
    // 7. out = (P / Z) @ u   (batched, causal K-limit, epilogue 1/Z)
    sgemm_nn<<<dim3(E / 128, T / 128, BBATCH), 256>>>(
        P, u, out, T, E, T,
        (long long)T * T, (long long)T * E, (long long)T * E, Z, 1);
}

// round 3
// speedup vs baseline: 2.7362x; 2.7362x over previous
#include <cuda_runtime.h>
#include <cuda_bf16.h>
#include <stdint.h>
#include <math.h>

// Problem constants: B=4, T=2048, E=1024, H*D=1024
#define BBATCH 4
#define TSEQ   2048
#define EDIM   1024
#define MTOK   (BBATCH * TSEQ)          // 8192 token rows

// ---------------------------------------------------------------------------
// Scratch (device globals, zero-initialized at module load)
// ---------------------------------------------------------------------------
__device__ __nv_bfloat16 g_xh [MTOK * EDIM];
__device__ __nv_bfloat16 g_xl [MTOK * EDIM];
__device__ __nv_bfloat16 g_wjh[EDIM * EDIM];
__device__ __nv_bfloat16 g_wjl[EDIM * EDIM];
__device__ __nv_bfloat16 g_woh[EDIM * EDIM];
__device__ __nv_bfloat16 g_wol[EDIM * EDIM];
__device__ __nv_bfloat16 g_wvth[EDIM * EDIM];           // wjv^T split
__device__ __nv_bfloat16 g_wvtl[EDIM * EDIM];
__device__ __nv_bfloat16 g_Wch[EDIM * EDIM];            // (wo@wjv) split
__device__ __nv_bfloat16 g_Wcl[EDIM * EDIM];
__device__ __nv_bfloat16 g_uh [EDIM * MTOK];            // u^T split
__device__ __nv_bfloat16 g_ul [EDIM * MTOK];
__device__ __nv_bfloat16 g_Ph [(size_t)BBATCH * TSEQ * TSEQ];
__device__ __nv_bfloat16 g_Pl [(size_t)BBATCH * TSEQ * TSEQ];
__device__ float g_scpart[8 * MTOK];
__device__ float g_sc  [MTOK];
__device__ float g_cmax[MTOK];
__device__ float g_Z   [MTOK];

// ---------------------------------------------------------------------------
// helpers
// ---------------------------------------------------------------------------
__device__ __forceinline__ uint32_t smem_u32(const void* p) {
    uint32_t a;
    asm("{ .reg .u64 t; cvta.to.shared.u64 t, %1; cvt.u32.u64 %0, t; }"
        : "=r"(a) : "l"(p));
    return a;
}
__device__ __forceinline__ uint32_t SWZ(uint32_t x) { return x ^ ((x >> 3) & 0x70); }

__device__ __forceinline__ void cp16(uint32_t dst, const void* src) {
    asm volatile("cp.async.cg.shared.global [%0], [%1], 16;" :: "r"(dst), "l"(src) : "memory");
}
#define CP_COMMIT() asm volatile("cp.async.commit_group;" ::: "memory")
#define CP_WAIT1()  asm volatile("cp.async.wait_group 1;" ::: "memory")

__device__ __forceinline__ void ldm_x4(uint32_t* r, uint32_t addr) {
    asm volatile("ldmatrix.sync.aligned.m8n8.x4.shared.b16 {%0,%1,%2,%3}, [%4];"
                 : "=r"(r[0]), "=r"(r[1]), "=r"(r[2]), "=r"(r[3]) : "r"(addr));
}
__device__ __forceinline__ void mma16816(float* d, const uint32_t* a, const uint32_t* b) {
    asm volatile(
        "mma.sync.aligned.m16n8k16.row.col.f32.bf16.bf16.f32 "
        "{%0,%1,%2,%3}, {%4,%5,%6,%7}, {%8,%9}, {%0,%1,%2,%3};"
        : "+f"(d[0]), "+f"(d[1]), "+f"(d[2]), "+f"(d[3])
        : "r"(a[0]), "r"(a[1]), "r"(a[2]), "r"(a[3]), "r"(b[0]), "r"(b[1]));
}

// ---------------------------------------------------------------------------
// NT tensor-core GEMM (mma.sync bf16, fp32 accum), 3 K-segments summed:
//   C[m,n] = sum_s A_s[m,:] . B_s[n,:]
// CTA tile M=128 N=128, K chunks of 64, 3-stage cp.async pipeline.
// EPI 0: row sum-of-squares -> scpart[bx*MTOK + row]
// EPI 1: bf16 hi/lo split store (Ohi/Olo), leading dim ldo
// EPI 2: fp32 store with 1/Z row scale into Cout (leading dim ldc)
// ---------------------------------------------------------------------------
#define STAGE 32768
#define SMEM_BYTES (3 * STAGE)

template <int EPI>
__global__ __launch_bounds__(256) void tc_gemm(
    const __nv_bfloat16* __restrict__ A0, const __nv_bfloat16* __restrict__ A1,
    const __nv_bfloat16* __restrict__ A2,
    const __nv_bfloat16* __restrict__ B0, const __nv_bfloat16* __restrict__ B1,
    const __nv_bfloat16* __restrict__ B2,
    int lda, int ldb, int Kseg, int causal,
    long long aStride, long long bColStride, long long cStride,
    float* __restrict__ scpart,
    __nv_bfloat16* __restrict__ Ohi, __nv_bfloat16* __restrict__ Olo, int ldo,
    float* __restrict__ Cout, const float* __restrict__ Zbase, int ldc)
{
    extern __shared__ __align__(1024) char dsm[];
    const uint32_t sbase = smem_u32(dsm);
    const int tid  = threadIdx.x;
    const int lane = tid & 31;
    const int wid  = tid >> 5;
    const int warp_m = wid & 1;        // 2 x 64 rows
    const int warp_n = wid >> 1;       // 4 x 32 cols
    const int m0 = blockIdx.y * 128;
    const int n0 = blockIdx.x * 128;
    const int z  = blockIdx.z;

    const __nv_bfloat16* Aarr[3] = {A0 + z * aStride, A1 + z * aStride, A2 + z * aStride};
    const __nv_bfloat16* Barr[3] = {B0, B1, B2};
    const long long bcol = (long long)z * bColStride;

    const int kEnd = causal ? ((m0 + 128 < Kseg) ? m0 + 128 : Kseg) : Kseg;
    const int nch = kEnd >> 6;
    const int n   = 3 * nch;

    float acc[4][4][4];
#pragma unroll
    for (int a = 0; a < 4; ++a)
#pragma unroll
        for (int b = 0; b < 4; ++b)
#pragma unroll
            for (int c = 0; c < 4; ++c) acc[a][b][c] = 0.f;

    auto load_chunk = [&](int j) {
        const int st  = j % 3;
        const int seg = j / nch;
        const int kc  = (j - seg * nch) << 6;
        const uint32_t sA = sbase + st * STAGE;
        const __nv_bfloat16* As = Aarr[seg];
        const __nv_bfloat16* Bs = Barr[seg];
#pragma unroll
        for (int i = 0; i < 4; ++i) {           // A: 128 rows x 128B
            int id = i * 256 + tid;
            int row = id >> 3, ch = id & 7;
            cp16(sA + SWZ(row * 128 + ch * 16),
                 As + (size_t)(m0 + row) * lda + kc + ch * 8);
        }
#pragma unroll
        for (int i = 0; i < 4; ++i) {           // B: 128 rows x 128B
            int id = i * 256 + tid;
            int row = id >> 3, ch = id & 7;
            cp16(sA + 16384 + SWZ(row * 128 + ch * 16),
                 Bs + (size_t)(n0 + row) * ldb + bcol + kc + ch * 8);
        }
    };

    // per-lane ldmatrix row/sel invariants
    const int arow = warp_m * 64 + (lane & 15);
    const int asel = lane >> 4;
    const int brow = warp_n * 32 + ((lane >> 4) << 3) + (lane & 7);
    const int bsel = (lane >> 3) & 1;

    load_chunk(0); CP_COMMIT();
    load_chunk(1); CP_COMMIT();

    for (int j = 0; j < n; ++j) {
        CP_WAIT1();
        __syncthreads();
        if (j + 2 < n) load_chunk(j + 2);
        CP_COMMIT();

        const uint32_t sA = sbase + (j % 3) * STAGE;
        const uint32_t sB = sA + 16384;
#pragma unroll
        for (int ks = 0; ks < 4; ++ks) {
            uint32_t afr[4][4], bfr[2][4];
#pragma unroll
            for (int mt = 0; mt < 4; ++mt)
                ldm_x4(afr[mt], sA + SWZ((arow + mt * 16) * 128 + (ks * 2 + asel) * 16));
#pragma unroll
            for (int p = 0; p < 2; ++p)
                ldm_x4(bfr[p], sB + SWZ((brow + p * 16) * 128 + (ks * 2 + bsel) * 16));
#pragma unroll
            for (int mt = 0; mt < 4; ++mt)
#pragma unroll
                for (int nt = 0; nt < 4; ++nt)
                    mma16816(acc[mt][nt], afr[mt], &bfr[nt >> 1][(nt & 1) * 2]);
        }
    }
    __syncthreads();   // stage smem free; also all accs done before epilogue reuse

    const int rbase = warp_m * 64 + (lane >> 2);
    const int cbase = warp_n * 32 + (lane & 3) * 2;

    if (EPI == 0) {
        float* red = (float*)dsm;   // [4 warp_n][128 rows]
#pragma unroll
        for (int mt = 0; mt < 4; ++mt) {
#pragma unroll
            for (int h = 0; h < 2; ++h) {
                float s = 0.f;
#pragma unroll
                for (int nt = 0; nt < 4; ++nt) {
                    float d0 = acc[mt][nt][2 * h], d1 = acc[mt][nt][2 * h + 1];
                    s = fmaf(d0, d0, fmaf(d1, d1, s));
                }
                s += __shfl_xor_sync(0xffffffffu, s, 1);
                s += __shfl_xor_sync(0xffffffffu, s, 2);
                if ((lane & 3) == 0)
                    red[warp_n * 128 + warp_m * 64 + mt * 16 + h * 8 + (lane >> 2)] = s;
            }
        }
        __syncthreads();
        if (tid < 128) {
            float s = red[tid] + red[128 + tid] + red[256 + tid] + red[384 + tid];
            scpart[(size_t)blockIdx.x * MTOK + m0 + tid] = s;
        }
    } else if (EPI == 1) {
#pragma unroll
        for (int mt = 0; mt < 4; ++mt)
#pragma unroll
            for (int h = 0; h < 2; ++h) {
                int row = m0 + rbase + mt * 16 + h * 8;
#pragma unroll
                for (int nt = 0; nt < 4; ++nt) {
                    float v0 = acc[mt][nt][2 * h], v1 = acc[mt][nt][2 * h + 1];
                    __nv_bfloat16 h0 = __float2bfloat16(v0);
                    __nv_bfloat16 h1 = __float2bfloat16(v1);
                    __nv_bfloat162 hp; hp.x = h0; hp.y = h1;
                    __nv_bfloat162 lp;
                    lp.x = __float2bfloat16(v0 - __bfloat162float(h0));
                    lp.y = __float2bfloat16(v1 - __bfloat162float(h1));
                    size_t off = (size_t)row * ldo + n0 + cbase + nt * 8;
                    *(__nv_bfloat162*)(Ohi + off) = hp;
                    *(__nv_bfloat162*)(Olo + off) = lp;
                }
            }
    } else {
#pragma unroll
        for (int mt = 0; mt < 4; ++mt)
#pragma unroll
            for (int h = 0; h < 2; ++h) {
                int row = m0 + rbase + mt * 16 + h * 8;
                float scale = 1.f / Zbase[(size_t)z * TSEQ + row];
                float* Cp = Cout + (size_t)z * cStride + (size_t)row * ldc + n0 + cbase;
#pragma unroll
                for (int nt = 0; nt < 4; ++nt) {
                    float2 v = make_float2(acc[mt][nt][2 * h] * scale,
                                           acc[mt][nt][2 * h + 1] * scale);
                    *(float2*)(Cp + nt * 8) = v;
                }
            }
    }
}

// ---------------------------------------------------------------------------
// fp32 -> bf16 hi/lo split
// ---------------------------------------------------------------------------
__global__ __launch_bounds__(256) void split_kernel(
    const float* __restrict__ src, __nv_bfloat16* __restrict__ hi,
    __nv_bfloat16* __restrict__ lo, int n)
{
    int i = (blockIdx.x * 256 + threadIdx.x) * 4;
    if (i >= n) return;
    float4 v = *(const float4*)(src + i);
    __nv_bfloat16 h0 = __float2bfloat16(v.x), h1 = __float2bfloat16(v.y);
    __nv_bfloat16 h2 = __float2bfloat16(v.z), h3 = __float2bfloat16(v.w);
    __nv_bfloat162 ha; ha.x = h0; ha.y = h1;
    __nv_bfloat162 hb; hb.x = h2; hb.y = h3;
    __nv_bfloat162 la, lb;
    la.x = __float2bfloat16(v.x - __bfloat162float(h0));
    la.y = __float2bfloat16(v.y - __bfloat162float(h1));
    lb.x = __float2bfloat16(v.z - __bfloat162float(h2));
    lb.y = __float2bfloat16(v.w - __bfloat162float(h3));
    *(__nv_bfloat162*)(hi + i)     = ha;
    *(__nv_bfloat162*)(hi + i + 2) = hb;
    *(__nv_bfloat162*)(lo + i)     = la;
    *(__nv_bfloat162*)(lo + i + 2) = lb;
}

// transpose + split: dst[j,k] = src[k,j]   (1024 x 1024)
__global__ __launch_bounds__(256) void transpose_split_kernel(
    const float* __restrict__ src, __nv_bfloat16* __restrict__ th,
    __nv_bfloat16* __restrict__ tl)
{
    __shared__ float tile[32][33];
    int x = blockIdx.x * 32 + threadIdx.x;
    int y0 = blockIdx.y * 32 + threadIdx.y;
#pragma unroll
    for (int i = 0; i < 4; ++i)
        tile[threadIdx.y + i * 8][threadIdx.x] = src[(size_t)(y0 + i * 8) * EDIM + x];
    __syncthreads();
    int ox = blockIdx.y * 32 + threadIdx.x;
    int oy0 = blockIdx.x * 32 + threadIdx.y;
#pragma unroll
    for (int i = 0; i < 4; ++i) {
        float v = tile[threadIdx.x][threadIdx.y + i * 8];
        __nv_bfloat16 h = __float2bfloat16(v);
        th[(size_t)(oy0 + i * 8) * EDIM + ox] = h;
        tl[(size_t)(oy0 + i * 8) * EDIM + ox] = __float2bfloat16(v - __bfloat162float(h));
    }
}

// sc[t] = (sum of 8 partials) / 32
__global__ __launch_bounds__(256) void sc_reduce_kernel()
{
    int t = blockIdx.x * 256 + threadIdx.x;
    float s = 0.f;
#pragma unroll
    for (int p = 0; p < 8; ++p) s += g_scpart[p * MTOK + t];
    g_sc[t] = s * 0.03125f;
}

// inclusive per-batch cummax
__global__ __launch_bounds__(1024) void cummax_kernel()
{
    __shared__ float s[TSEQ];
    const int b = blockIdx.x, tid = threadIdx.x;
    s[tid]        = g_sc[b * TSEQ + tid];
    s[tid + 1024] = g_sc[b * TSEQ + tid + 1024];
    __syncthreads();
    for (int off = 1; off < TSEQ; off <<= 1) {
        float v0 = s[tid];
        if (tid >= off) v0 = fmaxf(v0, s[tid - off]);
        float v1 = fmaxf(s[tid + 1024], s[tid + 1024 - off]);
        __syncthreads();
        s[tid] = v0; s[tid + 1024] = v1;
        __syncthreads();
    }
    g_cmax[b * TSEQ + tid]        = s[tid];
    g_cmax[b * TSEQ + tid + 1024] = s[tid + 1024];
}

// P (bf16 hi/lo, causal) + row sums Z
__global__ __launch_bounds__(256) void pgen_kernel()
{
    const int b = blockIdx.y;
    const int t0 = blockIdx.x * 32;
    const int warp = threadIdx.x >> 5, lane = threadIdx.x & 31;
    const float* scb = g_sc + b * TSEQ;
#pragma unroll
    for (int r = 0; r < 4; ++r) {
        const int t = t0 + warp * 4 + r;
        const float st = scb[t];
        const float m = st * g_cmax[b * TSEQ + t];
        float rowsum = 0.f;
        __nv_bfloat16* Ph = g_Ph + ((size_t)(b * TSEQ + t)) * TSEQ;
        __nv_bfloat16* Pl = g_Pl + ((size_t)(b * TSEQ + t)) * TSEQ;
        for (int sb = lane * 4; sb <= t; sb += 128) {
            float4 sv = *(const float4*)&scb[sb];
            float4 p;
            p.x = (sb + 0 <= t) ? __expf(fmaf(st, sv.x, -m)) : 0.f;
            p.y = (sb + 1 <= t) ? __expf(fmaf(st, sv.y, -m)) : 0.f;
            p.z = (sb + 2 <= t) ? __expf(fmaf(st, sv.z, -m)) : 0.f;
            p.w = (sb + 3 <= t) ? __expf(fmaf(st, sv.w, -m)) : 0.f;
            rowsum += (p.x + p.y) + (p.z + p.w);
            __nv_bfloat16 h0 = __float2bfloat16(p.x), h1 = __float2bfloat16(p.y);
            __nv_bfloat16 h2 = __float2bfloat16(p.z), h3 = __float2bfloat16(p.w);
            __nv_bfloat162 ha; ha.x = h0; ha.y = h1;
            __nv_bfloat162 hb; hb.x = h2; hb.y = h3;
            __nv_bfloat162 la, lb;
            la.x = __float2bfloat16(p.x - __bfloat162float(h0));
            la.y = __float2bfloat16(p.y - __bfloat162float(h1));
            lb.x = __float2bfloat16(p.z - __bfloat162float(h2));
            lb.y = __float2bfloat16(p.w - __bfloat162float(h3));
            *(__nv_bfloat162*)(Ph + sb)     = ha;
            *(__nv_bfloat162*)(Ph + sb + 2) = hb;
            *(__nv_bfloat162*)(Pl + sb)     = la;
            *(__nv_bfloat162*)(Pl + sb + 2) = lb;
        }
#pragma unroll
        for (int o = 16; o; o >>= 1)
            rowsum += __shfl_xor_sync(0xffffffffu, rowsum, o);
        if (lane == 0) g_Z[b * TSEQ + t] = rowsum;
    }
}

// ---------------------------------------------------------------------------
// launch
// ---------------------------------------------------------------------------
extern "C" void kernel_launch(void* const* d_in, const int* in_sizes, int n_in,
                              void* d_out, int out_size)
{
    const float* x   = (const float*)d_in[0];
    const float* wj  = (const float*)d_in[1];
    const float* wjv = (const float*)d_in[2];
    const float* wo  = (const float*)d_in[3];
    float* out = (float*)d_out;

    __nv_bfloat16 *xh, *xl, *wjh, *wjl, *woh, *wol, *wvth, *wvtl, *Wch, *Wcl,
                  *uh, *ul, *Ph, *Pl;
    float *scpart, *Z;
    cudaGetSymbolAddress((void**)&xh, g_xh);   cudaGetSymbolAddress((void**)&xl, g_xl);
    cudaGetSymbolAddress((void**)&wjh, g_wjh); cudaGetSymbolAddress((void**)&wjl, g_wjl);
    cudaGetSymbolAddress((void**)&woh, g_woh); cudaGetSymbolAddress((void**)&wol, g_wol);
    cudaGetSymbolAddress((void**)&wvth, g_wvth); cudaGetSymbolAddress((void**)&wvtl, g_wvtl);
    cudaGetSymbolAddress((void**)&Wch, g_Wch); cudaGetSymbolAddress((void**)&Wcl, g_Wcl);
    cudaGetSymbolAddress((void**)&uh, g_uh);   cudaGetSymbolAddress((void**)&ul, g_ul);
    cudaGetSymbolAddress((void**)&Ph, g_Ph);   cudaGetSymbolAddress((void**)&Pl, g_Pl);
    cudaGetSymbolAddress((void**)&scpart, g_scpart);
    cudaGetSymbolAddress((void**)&Z, g_Z);

    cudaFuncSetAttribute(tc_gemm<0>, cudaFuncAttributeMaxDynamicSharedMemorySize, SMEM_BYTES);
    cudaFuncSetAttribute(tc_gemm<1>, cudaFuncAttributeMaxDynamicSharedMemorySize, SMEM_BYTES);
    cudaFuncSetAttribute(tc_gemm<2>, cudaFuncAttributeMaxDynamicSharedMemorySize, SMEM_BYTES);

    // 1. splits
    split_kernel<<<MTOK * EDIM / 1024, 256>>>(x, xh, xl, MTOK * EDIM);
    split_kernel<<<EDIM * EDIM / 1024, 256>>>(wj, wjh, wjl, EDIM * EDIM);
    split_kernel<<<EDIM * EDIM / 1024, 256>>>(wo, woh, wol, EDIM * EDIM);
    transpose_split_kernel<<<dim3(32, 32), dim3(32, 8)>>>(wjv, wvth, wvtl);

    // 2. sc partials: ||x@wj^T||^2 row-norm pieces  (M=8192, N=1024, K=3x1024)
    tc_gemm<0><<<dim3(8, 64, 1), 256, SMEM_BYTES>>>(
        xh, xh, xl, wjh, wjl, wjh, EDIM, EDIM, EDIM, 0, 0, 0, 0,
        scpart, nullptr, nullptr, 0, nullptr, nullptr, 0);
    sc_reduce_kernel<<<MTOK / 256, 256>>>();
    cummax_kernel<<<BBATCH, 1024>>>();
    pgen_kernel<<<dim3(TSEQ / 32, BBATCH), 256>>>();

    // 3. Wc = wo @ wjv  (NT vs wjv^T) -> bf16 split
    tc_gemm<1><<<dim3(8, 8, 1), 256, SMEM_BYTES>>>(
        woh, woh, wol, wvth, wvtl, wvth, EDIM, EDIM, EDIM, 0, 0, 0, 0,
        nullptr, Wch, Wcl, EDIM, nullptr, nullptr, 0);

    // 4. u^T = Wc @ x^T  (M=1024 e-rows, N=8192 tokens) -> bf16 split
    tc_gemm<1><<<dim3(64, 8, 1), 256, SMEM_BYTES>>>(
        Wch, Wch, Wcl, xh, xl, xh, EDIM, EDIM, EDIM, 0, 0, 0, 0,
        nullptr, uh, ul, MTOK, nullptr, nullptr, 0);

    // 5. out = (P/Z) @ u  (batched causal; M=T, N=1024, K<=T)
    tc_gemm<2><<<dim3(8, TSEQ / 128, BBATCH), 256, SMEM_BYTES>>>(
        Ph, Ph, Pl, uh, ul, uh, TSEQ, MTOK, TSEQ, 1,
        (long long)TSEQ * TSEQ, (long long)TSEQ, (long long)TSEQ * EDIM,
        nullptr, nullptr, nullptr, 0, out, Z, EDIM);
}